// round 7
// baseline (speedup 1.0000x reference)
#include <cuda_runtime.h>
#include <cuda_bf16.h>

#define RM_EPS 1e-10f
#define MIN_DEPTH 0.1f
#define MAX_DEPTH 100.0f

constexpr int S_SAMP = 128;        // samples per ray
constexpr int S_INT  = S_SAMP - 1; // 127 intervals
constexpr int THREADS_PER_BLOCK = 128;   // 4 warps

// One warp per ray, strided lane->interval mapping (lane l owns intervals
// l, l+32, l+64, l+96). Zero shared memory:
//  - dl/depth neighbors (i+1) via __shfl_down (+ lane31 cross-chunk patch)
//  - colors via the regrouping identity  sum_i w_i*(c_i+c_{i+1})/2
//      = sum_s c_s*(w_{s-1}+w_s)/2,  so each lane touches only its OWN
//    sample's 3 color floats (w_prev is one shfl_up).
//  - cumprod: 4 independent 5-step warp scans (ILP), carries combined after.
__global__ __launch_bounds__(THREADS_PER_BLOCK)
void mip_ray_marcher_kernel(const float* __restrict__ colors,
                            const float* __restrict__ dlog,
                            const float* __restrict__ depths,
                            float* __restrict__ out,
                            int n_rays)
{
    const unsigned FULL = 0xffffffffu;
    const int lane = threadIdx.x & 31;
    const int ray  = (blockIdx.x * THREADS_PER_BLOCK + threadIdx.x) >> 5;
    if (ray >= n_rays) return;

    const float* dlr = dlog   + (size_t)ray * S_SAMP;
    const float* dpr = depths + (size_t)ray * S_SAMP;
    const float* cr  = colors + (size_t)ray * (S_SAMP * 3);

    // ---- coalesced direct loads ----
    float dlv[4], dpv[4];
    #pragma unroll
    for (int k = 0; k < 4; k++) {
        dlv[k] = dlr[lane + 32 * k];
        dpv[k] = dpr[lane + 32 * k];
    }

    // ---- neighbor (i+1) values via shuffles ----
    float dln[4], dpn[4];
    #pragma unroll
    for (int k = 0; k < 4; k++) {
        dln[k] = __shfl_down_sync(FULL, dlv[k], 1);
        dpn[k] = __shfl_down_sync(FULL, dpv[k], 1);
    }
    #pragma unroll
    for (int k = 0; k < 3; k++) {   // lane31's neighbor = next chunk lane0
        float a = __shfl_sync(FULL, dlv[k + 1], 0);
        float b = __shfl_sync(FULL, dpv[k + 1], 0);
        if (lane == 31) { dln[k] = a; dpn[k] = b; }
    }
    // k=3,lane31 (interval 127) is invalid; masked below.

    // ---- alpha / (1-alpha+eps) per interval ----
    float aarr[4], om[4];
    #pragma unroll
    for (int k = 0; k < 4; k++) {
        const bool valid = (lane + 32 * k) < S_INT;
        float dlm  = 0.5f * (dlv[k] + dln[k]) - 1.0f;
        float dens = fmaxf(dlm, 0.0f) + log1pf(expf(-fabsf(dlm)));  // softplus
        float a    = 1.0f - expf(-dens * (dpn[k] - dpv[k]));
        aarr[k] = valid ? a : 0.0f;
        om[k]   = valid ? (1.0f - a + RM_EPS) : 1.0f;  // scan identity
    }

    // ---- 4 independent inclusive warp scans (cumprod), ILP-interleaved ----
    float incl[4];
    #pragma unroll
    for (int k = 0; k < 4; k++) incl[k] = om[k];
    #pragma unroll
    for (int off = 1; off < 32; off <<= 1) {
        #pragma unroll
        for (int k = 0; k < 4; k++) {
            float v = __shfl_up_sync(FULL, incl[k], off);
            if (lane >= off) incl[k] *= v;
        }
    }

    // ---- combine chunk carries -> weights ----
    float wt[4];
    float carry = 1.0f;
    #pragma unroll
    for (int k = 0; k < 4; k++) {
        float excl = __shfl_up_sync(FULL, incl[k], 1);
        if (lane == 0) excl = 1.0f;
        float T = carry * excl;
        carry *= __shfl_sync(FULL, incl[k], 31);
        const bool valid = (lane + 32 * k) < S_INT;
        wt[k] = valid ? (aarr[k] + RM_EPS) * T : 0.0f;  // exact 0 for regroup
    }

    // ---- output offsets (flattened tuple, float32) ----
    const size_t NR      = (size_t)n_rays;
    const size_t OFF_RGB = 0;
    const size_t OFF_D   = 3 * NR;
    const size_t OFF_W   = 4 * NR;
    const size_t OFF_WA  = OFF_W  + NR * S_INT;
    const size_t OFF_A   = OFF_WA + NR * S_INT;
    const size_t OFF_DM  = OFF_A  + NR * S_INT;
    const size_t rb      = (size_t)ray * S_INT;

    float r0 = 0.f, r1 = 0.f, r2 = 0.f, wsum = 0.f, wdsum = 0.f;

    #pragma unroll
    for (int k = 0; k < 4; k++) {
        const int  i     = lane + 32 * k;       // interval & sample index
        const bool valid = (i < S_INT);

        float dmid = 0.5f * (dpv[k] + dpn[k]);
        wsum  += wt[k];                          // wt==0 when invalid
        wdsum += wt[k] * dmid;

        if (valid) {                             // coalesced streaming stores
            __stcs(out + OFF_W  + rb + i, wt[k]);
            __stcs(out + OFF_WA + rb + i, wt[k]);
            __stcs(out + OFF_A  + rb + i, aarr[k]);
            __stcs(out + OFF_DM + rb + i, dmid);
        }

        // regrouped color composite: h_s = (w_{s-1} + w_s)/2
        float wprev = __shfl_up_sync(FULL, wt[k], 1);
        float wlast = (k > 0) ? __shfl_sync(FULL, wt[k - 1], 31) : 0.0f;
        if (lane == 0) wprev = wlast;
        float h = 0.5f * (wt[k] + wprev);

        r0 += h * cr[3 * i + 0];
        r1 += h * cr[3 * i + 1];
        r2 += h * cr[3 * i + 2];
    }

    // ---- warp reductions (5 scalars) ----
    #pragma unroll
    for (int off = 16; off; off >>= 1) {
        wsum  += __shfl_xor_sync(FULL, wsum, off);
        wdsum += __shfl_xor_sync(FULL, wdsum, off);
        r0    += __shfl_xor_sync(FULL, r0, off);
        r1    += __shfl_xor_sync(FULL, r1, off);
        r2    += __shfl_xor_sync(FULL, r2, off);
    }

    if (lane == 0) {
        out[OFF_RGB + (size_t)ray * 3 + 0] = r0 * 2.0f - 1.0f;
        out[OFF_RGB + (size_t)ray * 3 + 1] = r1 * 2.0f - 1.0f;
        out[OFF_RGB + (size_t)ray * 3 + 2] = r2 * 2.0f - 1.0f;
        float d = wdsum / (RM_EPS + wsum);
        if (!(d == d)) d = MAX_DEPTH;               // nan_to_num
        d = fminf(fmaxf(d, MIN_DEPTH), MAX_DEPTH);  // clip
        out[OFF_D + ray] = d;
    }
}

extern "C" void kernel_launch(void* const* d_in, const int* in_sizes, int n_in,
                              void* d_out, int out_size)
{
    const float* colors = (const float*)d_in[0];  // [B,R,S,3]
    const float* dlog   = (const float*)d_in[1];  // [B,R,S,1]
    const float* depths = (const float*)d_in[2];  // [B,R,S,1]
    float* out = (float*)d_out;

    int n_rays = in_sizes[1] / S_SAMP;            // B*R = 65536
    int warps_per_block = THREADS_PER_BLOCK / 32;
    int blocks = (n_rays + warps_per_block - 1) / warps_per_block;
    mip_ray_marcher_kernel<<<blocks, THREADS_PER_BLOCK>>>(
        colors, dlog, depths, out, n_rays);
}

// round 8
// speedup vs baseline: 1.0760x; 1.0760x over previous
#include <cuda_runtime.h>
#include <cuda_bf16.h>

#define RM_EPS 1e-10f
#define MIN_DEPTH 0.1f
#define MAX_DEPTH 100.0f

constexpr int S_SAMP = 128;        // samples per ray
constexpr int S_INT  = S_SAMP - 1; // 127 intervals
constexpr int THREADS_PER_BLOCK = 128;   // 4 warps

// One warp per ray, strided lane->interval mapping (lane l owns intervals
// l, l+32, l+64, l+96). Zero shared memory. All 20 loads front-issued
// (__ldcs, evict-first), MUFU-based softplus/alpha, 4 ILP'd warp cumprod
// scans, regrouped color composite so each lane touches only its own colors.
__global__ __launch_bounds__(THREADS_PER_BLOCK)
void mip_ray_marcher_kernel(const float* __restrict__ colors,
                            const float* __restrict__ dlog,
                            const float* __restrict__ depths,
                            float* __restrict__ out,
                            int n_rays)
{
    const unsigned FULL = 0xffffffffu;
    const int lane = threadIdx.x & 31;
    const int ray  = (blockIdx.x * THREADS_PER_BLOCK + threadIdx.x) >> 5;
    if (ray >= n_rays) return;

    const float* dlr = dlog   + (size_t)ray * S_SAMP;
    const float* dpr = depths + (size_t)ray * S_SAMP;
    const float* cr  = colors + (size_t)ray * (S_SAMP * 3);

    // ---- front-load EVERYTHING (20 independent LDGs in flight) ----
    float dlv[4], dpv[4], col[12];
    #pragma unroll
    for (int k = 0; k < 4; k++) {
        dlv[k] = __ldcs(dlr + lane + 32 * k);
        dpv[k] = __ldcs(dpr + lane + 32 * k);
    }
    #pragma unroll
    for (int k = 0; k < 4; k++) {
        const int i = lane + 32 * k;
        col[3 * k + 0] = __ldcs(cr + 3 * i + 0);
        col[3 * k + 1] = __ldcs(cr + 3 * i + 1);
        col[3 * k + 2] = __ldcs(cr + 3 * i + 2);
    }

    // ---- neighbor (i+1) values via shuffles ----
    float dln[4], dpn[4];
    #pragma unroll
    for (int k = 0; k < 4; k++) {
        dln[k] = __shfl_down_sync(FULL, dlv[k], 1);
        dpn[k] = __shfl_down_sync(FULL, dpv[k], 1);
    }
    #pragma unroll
    for (int k = 0; k < 3; k++) {   // lane31's neighbor = next chunk lane0
        float a = __shfl_sync(FULL, dlv[k + 1], 0);
        float b = __shfl_sync(FULL, dpv[k + 1], 0);
        if (lane == 31) { dln[k] = a; dpn[k] = b; }
    }
    // k=3,lane31 (interval 127) is invalid; masked below.

    // ---- alpha / (1-alpha+eps) / dmid per interval (MUFU fast math) ----
    float aarr[4], om[4], dmid[4];
    #pragma unroll
    for (int k = 0; k < 4; k++) {
        const bool valid = (lane + 32 * k) < S_INT;
        float dlm  = 0.5f * (dlv[k] + dln[k]) - 1.0f;   // |dlm| small: safe
        float dens = __logf(1.0f + __expf(dlm));        // softplus
        float a    = 1.0f - __expf(-dens * (dpn[k] - dpv[k]));
        aarr[k] = valid ? a : 0.0f;
        om[k]   = valid ? (1.0f - a + RM_EPS) : 1.0f;   // scan identity
        dmid[k] = 0.5f * (dpv[k] + dpn[k]);
    }

    // ---- 4 independent inclusive warp scans (cumprod), ILP-interleaved ----
    float incl[4];
    #pragma unroll
    for (int k = 0; k < 4; k++) incl[k] = om[k];
    #pragma unroll
    for (int off = 1; off < 32; off <<= 1) {
        #pragma unroll
        for (int k = 0; k < 4; k++) {
            float v = __shfl_up_sync(FULL, incl[k], off);
            if (lane >= off) incl[k] *= v;
        }
    }

    // ---- combine chunk carries -> weights ----
    float wt[4];
    float carry = 1.0f;
    #pragma unroll
    for (int k = 0; k < 4; k++) {
        float excl = __shfl_up_sync(FULL, incl[k], 1);
        if (lane == 0) excl = 1.0f;
        float T = carry * excl;
        carry *= __shfl_sync(FULL, incl[k], 31);
        const bool valid = (lane + 32 * k) < S_INT;
        wt[k] = valid ? (aarr[k] + RM_EPS) * T : 0.0f;  // exact 0 for regroup
    }

    // ---- output offsets (flattened tuple, float32) ----
    const size_t NR      = (size_t)n_rays;
    const size_t OFF_RGB = 0;
    const size_t OFF_D   = 3 * NR;
    const size_t OFF_W   = 4 * NR;
    const size_t OFF_WA  = OFF_W  + NR * S_INT;
    const size_t OFF_A   = OFF_WA + NR * S_INT;
    const size_t OFF_DM  = OFF_A  + NR * S_INT;
    const size_t rb      = (size_t)ray * S_INT;

    float r0 = 0.f, r1 = 0.f, r2 = 0.f, wsum = 0.f, wdsum = 0.f;

    #pragma unroll
    for (int k = 0; k < 4; k++) {
        const int  i     = lane + 32 * k;       // interval & sample index
        const bool valid = (i < S_INT);

        wsum  += wt[k];                          // wt==0 when invalid
        wdsum += wt[k] * dmid[k];

        if (valid) {                             // coalesced streaming stores
            __stcs(out + OFF_W  + rb + i, wt[k]);
            __stcs(out + OFF_WA + rb + i, wt[k]);
            __stcs(out + OFF_A  + rb + i, aarr[k]);
            __stcs(out + OFF_DM + rb + i, dmid[k]);
        }

        // regrouped color composite: h_s = (w_{s-1} + w_s)/2
        float wprev = __shfl_up_sync(FULL, wt[k], 1);
        float wlast = (k > 0) ? __shfl_sync(FULL, wt[k - 1], 31) : 0.0f;
        if (lane == 0) wprev = wlast;
        float h = 0.5f * (wt[k] + wprev);

        r0 += h * col[3 * k + 0];
        r1 += h * col[3 * k + 1];
        r2 += h * col[3 * k + 2];
    }

    // ---- warp reductions (5 scalars) ----
    #pragma unroll
    for (int off = 16; off; off >>= 1) {
        wsum  += __shfl_xor_sync(FULL, wsum, off);
        wdsum += __shfl_xor_sync(FULL, wdsum, off);
        r0    += __shfl_xor_sync(FULL, r0, off);
        r1    += __shfl_xor_sync(FULL, r1, off);
        r2    += __shfl_xor_sync(FULL, r2, off);
    }

    if (lane == 0) {
        out[OFF_RGB + (size_t)ray * 3 + 0] = r0 * 2.0f - 1.0f;
        out[OFF_RGB + (size_t)ray * 3 + 1] = r1 * 2.0f - 1.0f;
        out[OFF_RGB + (size_t)ray * 3 + 2] = r2 * 2.0f - 1.0f;
        float d = wdsum / (RM_EPS + wsum);
        if (!(d == d)) d = MAX_DEPTH;               // nan_to_num
        d = fminf(fmaxf(d, MIN_DEPTH), MAX_DEPTH);  // clip
        out[OFF_D + ray] = d;
    }
}

extern "C" void kernel_launch(void* const* d_in, const int* in_sizes, int n_in,
                              void* d_out, int out_size)
{
    const float* colors = (const float*)d_in[0];  // [B,R,S,3]
    const float* dlog   = (const float*)d_in[1];  // [B,R,S,1]
    const float* depths = (const float*)d_in[2];  // [B,R,S,1]
    float* out = (float*)d_out;

    int n_rays = in_sizes[1] / S_SAMP;            // B*R = 65536
    int warps_per_block = THREADS_PER_BLOCK / 32;
    int blocks = (n_rays + warps_per_block - 1) / warps_per_block;
    mip_ray_marcher_kernel<<<blocks, THREADS_PER_BLOCK>>>(
        colors, dlog, depths, out, n_rays);
}